// round 3
// baseline (speedup 1.0000x reference)
#include <cuda_runtime.h>

// Problem constants (MlaNer1): B=64, L=512, H2=1536, T=64
#define K_DIM 1536
#define N_DIM 64
#define BM 256
#define BK 16
#define NTHREADS 256
#define MAX_BLOCKS 512
#define WROW (2 * N_DIM)   // duplicated-W row: 128 floats per k

// packed fp32x2 FMA: d = a*b + d (per 32-bit lane), exact fp32 FMA semantics
#define FMA2(d, a, b) \
    asm("fma.rn.f32x2 %0, %1, %2, %0;" : "+l"(d) : "l"(a), "l"(b))

#define UNPACK2(lo, hi, in) \
    asm("mov.b64 {%0, %1}, %2;" : "=f"(lo), "=f"(hi) : "l"(in))

// Per-block partial reductions (deterministic: tree-reduced, no float atomics)
__device__ float g_partLoss[MAX_BLOCKS];
__device__ int   g_partRight[MAX_BLOCKS];
__device__ int   g_partCount[MAX_BLOCKS];

// Fused kernel: fp32 GEMM via packed FFMA2 (BM=256 x N=64, BK=16, 8x8
// micro-tile as 4x8 f32x2 pairs, double-buffered smem, W stored duplicated)
// + per-token softmax-stats epilogue + loss/acc.
__global__ __launch_bounds__(NTHREADS, 1)
void fused_kernel(const float* __restrict__ x,
                  const float* __restrict__ W,
                  const float* __restrict__ bias,
                  const int* __restrict__ tags,
                  const float* __restrict__ t2s,
                  const int* __restrict__ tptr,
                  int M)
{
    extern __shared__ float smem[];
    float* sXb[2] = { smem,                 smem + BK * BM };
    float* sWb[2] = { smem + 2 * BK * BM,   smem + 2 * BK * BM + BK * WROW };

    const int tid = threadIdx.x;
    const int m0  = blockIdx.x * BM;
    const int tm  = tid >> 3;   // 0..31 : 8-row group
    const int tn  = tid & 7;    // 0..7  : 8-col group

    int ldrow = m0 + tid;
    if (ldrow >= M) ldrow = M - 1;
    const float* xrow = x + (size_t)ldrow * K_DIM;

    const int wk = tid >> 4;           // 0..15
    const int wn = (tid & 15) << 2;    // 0,4,...,60

    // ---- preload chunk 0 into registers ----
    float4 rx0 = *(const float4*)(xrow + 0);
    float4 rx1 = *(const float4*)(xrow + 4);
    float4 rx2 = *(const float4*)(xrow + 8);
    float4 rx3 = *(const float4*)(xrow + 12);
    float4 rw  = *(const float4*)(W + (size_t)wk * N_DIM + wn);

    // accumulators: acc2[i][j] holds rows (2i, 2i+1) of col j, packed f32x2
    unsigned long long acc2[4][8];
    #pragma unroll
    for (int i = 0; i < 4; i++)
        #pragma unroll
        for (int j = 0; j < 8; j++) acc2[i][j] = 0ULL;

    const int NCHUNK = K_DIM / BK;  // 96
    int buf = 0;

    for (int c = 0; c < NCHUNK; ++c) {
        float* cx = sXb[buf];
        float* cw = sWb[buf];

        // stage x (transposed sX[k][m], conflict-free)
        cx[ 0 * BM + tid] = rx0.x; cx[ 1 * BM + tid] = rx0.y;
        cx[ 2 * BM + tid] = rx0.z; cx[ 3 * BM + tid] = rx0.w;
        cx[ 4 * BM + tid] = rx1.x; cx[ 5 * BM + tid] = rx1.y;
        cx[ 6 * BM + tid] = rx1.z; cx[ 7 * BM + tid] = rx1.w;
        cx[ 8 * BM + tid] = rx2.x; cx[ 9 * BM + tid] = rx2.y;
        cx[10 * BM + tid] = rx2.z; cx[11 * BM + tid] = rx2.w;
        cx[12 * BM + tid] = rx3.x; cx[13 * BM + tid] = rx3.y;
        cx[14 * BM + tid] = rx3.z; cx[15 * BM + tid] = rx3.w;
        // stage W DUPLICATED: cw[k][2j] = cw[k][2j+1] = W[k][j]
        {
            float4 d0 = make_float4(rw.x, rw.x, rw.y, rw.y);
            float4 d1 = make_float4(rw.z, rw.z, rw.w, rw.w);
            *(float4*)(cw + wk * WROW + 2 * wn)     = d0;
            *(float4*)(cw + wk * WROW + 2 * wn + 4) = d1;
        }

        __syncthreads();

        // prefetch next chunk (hidden under compute)
        if (c + 1 < NCHUNK) {
            const float* xp = xrow + (c + 1) * BK;
            rx0 = *(const float4*)(xp + 0);
            rx1 = *(const float4*)(xp + 4);
            rx2 = *(const float4*)(xp + 8);
            rx3 = *(const float4*)(xp + 12);
            rw  = *(const float4*)(W + ((size_t)(c + 1) * BK + wk) * N_DIM + wn);
        }

        // compute this chunk: 32 FFMA2 per k-step (64 FMAs)
        #pragma unroll
        for (int k = 0; k < BK; k++) {
            const ulonglong2 A0 = *(const ulonglong2*)(cx + k * BM + tm * 8);
            const ulonglong2 A1 = *(const ulonglong2*)(cx + k * BM + tm * 8 + 4);
            const float* wb = cw + k * WROW + tn * 16;
            const ulonglong2 W0 = *(const ulonglong2*)(wb);
            const ulonglong2 W1 = *(const ulonglong2*)(wb + 4);
            const ulonglong2 W2 = *(const ulonglong2*)(wb + 8);
            const ulonglong2 W3 = *(const ulonglong2*)(wb + 12);
            unsigned long long ap[4] = { A0.x, A0.y, A1.x, A1.y };
            unsigned long long wd[8] = { W0.x, W0.y, W1.x, W1.y,
                                         W2.x, W2.y, W3.x, W3.y };
            #pragma unroll
            for (int i = 0; i < 4; i++)
                #pragma unroll
                for (int j = 0; j < 8; j++)
                    FMA2(acc2[i][j], ap[i], wd[j]);
        }
        buf ^= 1;
    }

    // ---- epilogue: per-token softmax stats + loss + accuracy ----
    float bv[8];
    #pragma unroll
    for (int j = 0; j < 8; j++) bv[j] = bias[tn * 8 + j];

    const int   tval = *tptr;
    const float E1   = 2.718281828459045f;

    float myLoss = 0.f;
    int myRight = 0, myCount = 0;

    #pragma unroll
    for (int r = 0; r < 8; r++) {
        const int grow = m0 + tm * 8 + r;
        float v[8];
        float lmax = -1e30f;
        int   lidx = 0;
        float lsum = 0.f;
        #pragma unroll
        for (int j = 0; j < 8; j++) {
            float lo, hi;
            UNPACK2(lo, hi, acc2[r >> 1][j]);
            v[j] = ((r & 1) ? hi : lo) + bv[j];
            lsum += v[j];
            if (v[j] > lmax) { lmax = v[j]; lidx = tn * 8 + j; }
        }
        #pragma unroll
        for (int o = 1; o < 8; o <<= 1) {
            float om = __shfl_xor_sync(0xffffffffu, lmax, o, 8);
            int   oi = __shfl_xor_sync(0xffffffffu, lidx, o, 8);
            if (om > lmax || (om == lmax && oi < lidx)) { lmax = om; lidx = oi; }
        }
        float z = 0.f;
        #pragma unroll
        for (int j = 0; j < 8; j++) z += __expf(v[j] - lmax);
        #pragma unroll
        for (int o = 1; o < 8; o <<= 1) {
            z    += __shfl_xor_sync(0xffffffffu, z,    o, 8);
            lsum += __shfl_xor_sync(0xffffffffu, lsum, o, 8);
        }

        if (grow < M) {
            const int tg = tags[grow];
            if ((tg >> 3) == tn) {
                float ltag = v[0];
                #pragma unroll
                for (int j = 1; j < 8; j++) if ((tg & 7) == j) ltag = v[j];

                float logZ   = __logf(z);
                float lp_tag = ltag - lmax - logZ;
                float S_log  = lsum - 64.f * (lmax + logZ);
                float s  = t2s[tg];
                float sc = powf(s, (float)tval);
                float es = __expf(sc);
                float Zy = 63.f * E1 + es;
                float y_non = E1 / Zy;
                float y_hot = es / Zy;
                myLoss -= y_non * S_log + (y_hot - y_non) * lp_tag;
                if (tg < N_DIM - 3) { myCount++; if (lidx == tg) myRight++; }
            }
        }
    }

    // ---- deterministic block tree-reduction (reuse smem) ----
    __syncthreads();
    float* rl = smem;
    int*   rr = (int*)(smem + NTHREADS);
    int*   rc = (int*)(smem + 2 * NTHREADS);
    rl[tid] = myLoss; rr[tid] = myRight; rc[tid] = myCount;
    __syncthreads();
    #pragma unroll
    for (int s2 = NTHREADS / 2; s2 > 0; s2 >>= 1) {
        if (tid < s2) {
            rl[tid] += rl[tid + s2];
            rr[tid] += rr[tid + s2];
            rc[tid] += rc[tid + s2];
        }
        __syncthreads();
    }
    if (tid == 0) {
        g_partLoss[blockIdx.x]  = rl[0];
        g_partRight[blockIdx.x] = rr[0];
        g_partCount[blockIdx.x] = rc[0];
    }
}

__global__ void finalize_kernel(float* __restrict__ out, int nb)
{
    __shared__ float sl[256];
    __shared__ int   sr[256];
    __shared__ int   sc[256];
    const int t = threadIdx.x;
    float L = 0.f; int R = 0, C = 0;
    for (int i = t; i < nb; i += 256) {
        L += g_partLoss[i]; R += g_partRight[i]; C += g_partCount[i];
    }
    sl[t] = L; sr[t] = R; sc[t] = C;
    __syncthreads();
    for (int s = 128; s > 0; s >>= 1) {
        if (t < s) { sl[t] += sl[t + s]; sr[t] += sr[t + s]; sc[t] += sc[t + s]; }
        __syncthreads();
    }
    if (t == 0) {
        out[0] = sl[0];
        out[1] = (float)sr[0] / (float)sc[0];
    }
}

extern "C" void kernel_launch(void* const* d_in, const int* in_sizes, int n_in,
                              void* d_out, int out_size)
{
    // metadata order: x, W, b, tags, attention_mask, tag_to_score, t
    const float* x    = (const float*)d_in[0];
    const float* W    = (const float*)d_in[1];
    const float* b    = (const float*)d_in[2];
    const int*   tags = (const int*)d_in[3];
    // d_in[4] attention_mask: uniform additive shift over softmax axis -> no-op
    const float* t2s  = (const float*)d_in[5];
    const int*   tptr = (const int*)d_in[6];

    const int M = in_sizes[3];
    int nblocks = (M + BM - 1) / BM;
    if (nblocks > MAX_BLOCKS) nblocks = MAX_BLOCKS;

    // sX: 2*16*256 floats, sW(dup): 2*16*128 floats  => 48 KB
    const size_t smem_bytes = (size_t)(2 * BK * BM + 2 * BK * WROW) * sizeof(float);

    fused_kernel<<<nblocks, NTHREADS, smem_bytes>>>(x, W, b, tags, t2s, tptr, M);
    finalize_kernel<<<1, 256>>>((float*)d_out, nblocks);
}

// round 5
// speedup vs baseline: 2.9565x; 2.9565x over previous
#include <cuda_runtime.h>
#include <cstdint>

// MlaNer1: B=64, L=512, H2=1536, T=64 -> GEMM M=32768, N=64, K=1536
#define K_DIM   1536
#define N_DIM   64
#define BM      256              // CTA M-tile (8 warps x 32 rows)
#define BK      16               // K per chunk (2 k8-steps)
#define NCHUNK  (K_DIM / BK)     // 96
#define NTHREADS 256
#define MAX_BLOCKS 512
#define STRIDE  20               // smem row stride in floats (conflict-free, 16B-OK)

// smem float-offsets
#define F_BIAS  0
#define F_BUF   64
#define F_XHI   0
#define F_XLO   (BM * STRIDE)            // 5120
#define F_WHI   (2 * BM * STRIDE)        // 10240
#define F_WLO   (2 * BM * STRIDE + N_DIM * STRIDE)  // 11520
#define F_BUFSZ (2 * BM * STRIDE + 2 * N_DIM * STRIDE)  // 12800
#define SMEM_FLOATS (F_BUF + 2 * F_BUFSZ)               // 25664
#define SMEM_BYTES  (SMEM_FLOATS * 4)                   // 102656

__device__ float g_partLoss[MAX_BLOCKS];
__device__ int   g_partRight[MAX_BLOCKS];
__device__ int   g_partCount[MAX_BLOCKS];
// W transposed to [N,K] (k contiguous) and TF32-split
__device__ __align__(16) float g_Wt_hi[N_DIM * K_DIM];
__device__ __align__(16) float g_Wt_lo[N_DIM * K_DIM];

static __device__ __forceinline__ float tf32_rna(float f) {
    float r; asm("cvt.rna.tf32.f32 %0, %1;" : "=f"(r) : "f"(f)); return r;
}
// portable warp-level tensor op (sm_80+): D(f32) += A(tf32) * B(tf32)
static __device__ __forceinline__ void mma_tf32(float* c, const uint32_t* a,
                                                uint32_t b0, uint32_t b1) {
    asm volatile("mma.sync.aligned.m16n8k8.row.col.f32.tf32.tf32.f32 "
        "{%0,%1,%2,%3}, {%4,%5,%6,%7}, {%8,%9}, {%0,%1,%2,%3};"
        : "+f"(c[0]), "+f"(c[1]), "+f"(c[2]), "+f"(c[3])
        : "r"(a[0]), "r"(a[1]), "r"(a[2]), "r"(a[3]), "r"(b0), "r"(b1));
}

// ---- pre-kernel: transpose W [K,N] -> [N,K] and TF32-split ----
__global__ void split_w_kernel(const float* __restrict__ W) {
    int idx = blockIdx.x * blockDim.x + threadIdx.x;    // idx = n*K + k
    if (idx < N_DIM * K_DIM) {
        int n = idx / K_DIM;
        int k = idx - n * K_DIM;
        float w = W[(size_t)k * N_DIM + n];
        float h = tf32_rna(w);
        g_Wt_hi[idx] = h;
        g_Wt_lo[idx] = tf32_rna(w - h);
    }
}

// ---- fused 3xTF32 mma.sync GEMM + softmax-stats + loss/acc ----
__global__ __launch_bounds__(NTHREADS, 1)
void fused_kernel(const float* __restrict__ x,
                  const float* __restrict__ bias,
                  const int* __restrict__ tags,
                  const float* __restrict__ t2s,
                  const int* __restrict__ tptr,
                  int M)
{
    extern __shared__ float smem[];
    const int tid  = threadIdx.x;
    const int w    = tid >> 5;         // warp 0..7
    const int lane = tid & 31;
    const int g    = lane >> 2;        // group 0..7
    const int t    = lane & 3;         // thread-in-group
    const int m0   = blockIdx.x * BM;

    if (tid < N_DIM) smem[F_BIAS + tid] = bias[tid];

    // x staging: thread tid stages row tid (16 cols per chunk)
    int arow = m0 + tid; if (arow >= M) arow = M - 1;
    const float* xrow = x + (size_t)arow * K_DIM;
    // W staging: thread stages n = tid>>2, k4 = (tid&3)*4
    const int wn = tid >> 2;
    const int k4 = (tid & 3) * 4;
    const float* whp = g_Wt_hi + (size_t)wn * K_DIM + k4;
    const float* wlp = g_Wt_lo + (size_t)wn * K_DIM + k4;

    // accumulators: c[mt][nt][4]
    float acc[2][8][4];
    #pragma unroll
    for (int mt = 0; mt < 2; mt++)
        #pragma unroll
        for (int nt = 0; nt < 8; nt++)
            #pragma unroll
            for (int q = 0; q < 4; q++) acc[mt][nt][q] = 0.f;

    // prologue: LDG chunk 0
    float4 xa[4]; float4 wh, wl;
    #pragma unroll
    for (int q = 0; q < 4; q++) xa[q] = *(const float4*)(xrow + 4 * q);
    wh = *(const float4*)whp;
    wl = *(const float4*)wlp;

    int buf = 0;
    for (int c = 0; c < NCHUNK; ++c) {
        float* S = smem + F_BUF + buf * F_BUFSZ;

        // ---- stage: split x -> hi/lo, store; store pre-split W ----
        #pragma unroll
        for (int q = 0; q < 4; q++) {
            float4 f = xa[q];
            float4 h = make_float4(tf32_rna(f.x), tf32_rna(f.y), tf32_rna(f.z), tf32_rna(f.w));
            float4 l = make_float4(tf32_rna(f.x - h.x), tf32_rna(f.y - h.y),
                                   tf32_rna(f.z - h.z), tf32_rna(f.w - h.w));
            *(float4*)(S + F_XHI + tid * STRIDE + 4 * q) = h;
            *(float4*)(S + F_XLO + tid * STRIDE + 4 * q) = l;
        }
        *(float4*)(S + F_WHI + wn * STRIDE + k4) = wh;
        *(float4*)(S + F_WLO + wn * STRIDE + k4) = wl;

        __syncthreads();

        // prefetch next chunk
        if (c + 1 < NCHUNK) {
            const float* xp = xrow + (c + 1) * BK;
            #pragma unroll
            for (int q = 0; q < 4; q++) xa[q] = *(const float4*)(xp + 4 * q);
            wh = *(const float4*)(whp + (c + 1) * BK);
            wl = *(const float4*)(wlp + (c + 1) * BK);
        }

        // ---- compute: 2 k8-steps, 48 MMA each ----
        const uint32_t* Su = (const uint32_t*)S;
        #pragma unroll
        for (int ks = 0; ks < 2; ks++) {
            const int kc = ks * 8 + t;
            uint32_t ahi[2][4], alo[2][4];
            #pragma unroll
            for (int mt = 0; mt < 2; mt++) {
                const int r0 = (32 * w + 16 * mt + g) * STRIDE + kc;
                ahi[mt][0] = Su[F_XHI + r0];
                ahi[mt][1] = Su[F_XHI + r0 + 8 * STRIDE];
                ahi[mt][2] = Su[F_XHI + r0 + 4];
                ahi[mt][3] = Su[F_XHI + r0 + 8 * STRIDE + 4];
                alo[mt][0] = Su[F_XLO + r0];
                alo[mt][1] = Su[F_XLO + r0 + 8 * STRIDE];
                alo[mt][2] = Su[F_XLO + r0 + 4];
                alo[mt][3] = Su[F_XLO + r0 + 8 * STRIDE + 4];
            }
            uint32_t bhi[8][2], blo[8][2];
            #pragma unroll
            for (int nt = 0; nt < 8; nt++) {
                const int b0 = (8 * nt + g) * STRIDE + kc;
                bhi[nt][0] = Su[F_WHI + b0];
                bhi[nt][1] = Su[F_WHI + b0 + 4];
                blo[nt][0] = Su[F_WLO + b0];
                blo[nt][1] = Su[F_WLO + b0 + 4];
            }
            // term-major order: same-accumulator MMAs are 16 apart (no RAW stall)
            #pragma unroll
            for (int nt = 0; nt < 8; nt++)
                #pragma unroll
                for (int mt = 0; mt < 2; mt++)
                    mma_tf32(acc[mt][nt], ahi[mt], bhi[nt][0], bhi[nt][1]);
            #pragma unroll
            for (int nt = 0; nt < 8; nt++)
                #pragma unroll
                for (int mt = 0; mt < 2; mt++)
                    mma_tf32(acc[mt][nt], ahi[mt], blo[nt][0], blo[nt][1]);
            #pragma unroll
            for (int nt = 0; nt < 8; nt++)
                #pragma unroll
                for (int mt = 0; mt < 2; mt++)
                    mma_tf32(acc[mt][nt], alo[mt], bhi[nt][0], bhi[nt][1]);
        }
        buf ^= 1;
    }

    // ---- epilogue: each (quad, mt, half) owns one row; lane holds 16 cols:
    //      col = 8*nt + 2*t + j, val = acc[mt][nt][2*half + j] ----
    const int   tval = *tptr;
    const float E1   = 2.718281828459045f;
    float myLoss = 0.f;
    int myRight = 0, myCount = 0;

    #pragma unroll
    for (int mt = 0; mt < 2; mt++) {
        #pragma unroll
        for (int half = 0; half < 2; half++) {
            const int grow = m0 + 32 * w + 16 * mt + 8 * half + g;
            float v[16];
            float lmax = -1e30f, lsum = 0.f;
            int lidx = 0;
            #pragma unroll
            for (int nt = 0; nt < 8; nt++) {
                #pragma unroll
                for (int j = 0; j < 2; j++) {
                    const int col = 8 * nt + 2 * t + j;
                    float f = acc[mt][nt][2 * half + j] + smem[F_BIAS + col];
                    v[2 * nt + j] = f;
                    lsum += f;
                    if (f > lmax) { lmax = f; lidx = col; }
                }
            }
            // quad butterfly (width 4): max+argmax, then sums
            #pragma unroll
            for (int o = 1; o < 4; o <<= 1) {
                float om = __shfl_xor_sync(0xffffffffu, lmax, o, 4);
                int   oi = __shfl_xor_sync(0xffffffffu, lidx, o, 4);
                if (om > lmax || (om == lmax && oi < lidx)) { lmax = om; lidx = oi; }
            }
            float z = 0.f;
            #pragma unroll
            for (int q = 0; q < 16; q++) z += __expf(v[q] - lmax);
            #pragma unroll
            for (int o = 1; o < 4; o <<= 1) {
                z    += __shfl_xor_sync(0xffffffffu, z,    o, 4);
                lsum += __shfl_xor_sync(0xffffffffu, lsum, o, 4);
            }

            if (grow < M) {
                const int tg = tags[grow];
                if (((tg >> 1) & 3) == t) {     // this lane owns column tg
                    float ltag = v[0];
                    #pragma unroll
                    for (int nt = 0; nt < 8; nt++)
                        #pragma unroll
                        for (int j = 0; j < 2; j++)
                            if (tg == 8 * nt + 2 * t + j) ltag = v[2 * nt + j];

                    float logZ   = __logf(z);
                    float lp_tag = ltag - lmax - logZ;
                    float S_log  = lsum - 64.f * (lmax + logZ);
                    float s  = t2s[tg];
                    float sc = powf(s, (float)tval);
                    float es = __expf(sc);
                    float Zy = 63.f * E1 + es;
                    float y_non = E1 / Zy;
                    float y_hot = es / Zy;
                    myLoss -= y_non * S_log + (y_hot - y_non) * lp_tag;
                    if (tg < N_DIM - 3) { myCount++; if (lidx == tg) myRight++; }
                }
            }
        }
    }

    // ---- deterministic block tree-reduction (reuse stage smem) ----
    __syncthreads();
    float* rl = smem + F_BUF;
    int*   rr = (int*)(smem + F_BUF + NTHREADS);
    int*   rc = (int*)(smem + F_BUF + 2 * NTHREADS);
    rl[tid] = myLoss; rr[tid] = myRight; rc[tid] = myCount;
    __syncthreads();
    #pragma unroll
    for (int s2 = NTHREADS / 2; s2 > 0; s2 >>= 1) {
        if (tid < s2) { rl[tid] += rl[tid + s2]; rr[tid] += rr[tid + s2]; rc[tid] += rc[tid + s2]; }
        __syncthreads();
    }
    if (tid == 0) {
        g_partLoss[blockIdx.x]  = rl[0];
        g_partRight[blockIdx.x] = rr[0];
        g_partCount[blockIdx.x] = rc[0];
    }
}

__global__ void finalize_kernel(float* __restrict__ out, int nb)
{
    __shared__ float sl[256];
    __shared__ int   sr[256];
    __shared__ int   sc[256];
    const int t = threadIdx.x;
    float L = 0.f; int R = 0, C = 0;
    for (int i = t; i < nb; i += 256) {
        L += g_partLoss[i]; R += g_partRight[i]; C += g_partCount[i];
    }
    sl[t] = L; sr[t] = R; sc[t] = C;
    __syncthreads();
    for (int s = 128; s > 0; s >>= 1) {
        if (t < s) { sl[t] += sl[t + s]; sr[t] += sr[t + s]; sc[t] += sc[t + s]; }
        __syncthreads();
    }
    if (t == 0) {
        out[0] = sl[0];
        out[1] = (float)sr[0] / (float)sc[0];
    }
}

extern "C" void kernel_launch(void* const* d_in, const int* in_sizes, int n_in,
                              void* d_out, int out_size)
{
    // metadata order: x, W, b, tags, attention_mask, tag_to_score, t
    const float* x    = (const float*)d_in[0];
    const float* W    = (const float*)d_in[1];
    const float* b    = (const float*)d_in[2];
    const int*   tags = (const int*)d_in[3];
    // d_in[4] attention_mask: uniform additive shift over softmax axis -> no-op
    const float* t2s  = (const float*)d_in[5];
    const int*   tptr = (const int*)d_in[6];

    const int M = in_sizes[3];                   // 32768 tokens
    int nblocks = (M + BM - 1) / BM;             // 128
    if (nblocks > MAX_BLOCKS) nblocks = MAX_BLOCKS;

    cudaFuncSetAttribute(fused_kernel, cudaFuncAttributeMaxDynamicSharedMemorySize, SMEM_BYTES);

    split_w_kernel<<<(N_DIM * K_DIM + 255) / 256, 256>>>(W);
    fused_kernel<<<nblocks, NTHREADS, SMEM_BYTES>>>(x, b, tags, t2s, tptr, M);
    finalize_kernel<<<1, 256>>>((float*)d_out, nblocks);
}

// round 6
// speedup vs baseline: 4.1553x; 1.4055x over previous
#include <cuda_runtime.h>
#include <cuda_fp16.h>
#include <cstdint>

// MlaNer1: B=64, L=512, H2=1536, T=64 -> GEMM M=32768, N=64, K=1536
#define K_DIM   1536
#define N_DIM   64
#define BM      256              // CTA M-tile (8 warps x 32 rows)
#define BK      16               // K per chunk = one k16 MMA step
#define NCHUNK  (K_DIM / BK)     // 96
#define NTHREADS 256
#define MAX_BLOCKS 512
#define STRIDE_U 12              // u32 per row (8 data + 4 pad) — conflict-free

// W prescale: 2^10 (exact); logits descaled in epilogue
#define WSCALE   1024.0f
#define INV_WSCALE (1.0f / 1024.0f)

// smem u32-offsets
#define U_BIAS  0                 // 64 floats
#define U_BUF   64
#define U_XHI   0
#define U_XLO   (BM * STRIDE_U)                   // 3072
#define U_WHI   (2 * BM * STRIDE_U)               // 6144
#define U_WLO   (2 * BM * STRIDE_U + N_DIM * STRIDE_U)  // 6912
#define U_BUFSZ (2 * BM * STRIDE_U + 2 * N_DIM * STRIDE_U) // 7680
#define SMEM_U32 (U_BUF + 2 * U_BUFSZ)            // 15424
#define SMEM_BYTES (SMEM_U32 * 4)                 // 61696

__device__ float g_partLoss[MAX_BLOCKS];
__device__ int   g_partRight[MAX_BLOCKS];
__device__ int   g_partCount[MAX_BLOCKS];
// W transposed to [N,K], prescaled by 2^10, fp16-split, packed half2 (u32)
__device__ __align__(16) uint32_t g_Wp_hi[N_DIM * K_DIM / 2];
__device__ __align__(16) uint32_t g_Wp_lo[N_DIM * K_DIM / 2];

// D(f32) += A(f16) * B(f16) : m16n8k16, sm_80+ portable
static __device__ __forceinline__ void mma_f16(float* c, const uint32_t* a,
                                               const uint32_t* b) {
    asm volatile("mma.sync.aligned.m16n8k16.row.col.f32.f16.f16.f32 "
        "{%0,%1,%2,%3}, {%4,%5,%6,%7}, {%8,%9}, {%0,%1,%2,%3};"
        : "+f"(c[0]), "+f"(c[1]), "+f"(c[2]), "+f"(c[3])
        : "r"(a[0]), "r"(a[1]), "r"(a[2]), "r"(a[3]), "r"(b[0]), "r"(b[1]));
}

static __device__ __forceinline__ void split2(float f0, float f1,
                                              uint32_t& hi, uint32_t& lo) {
    __half2 h = __floats2half2_rn(f0, f1);
    float2  fh = __half22float2(h);
    __half2 l = __floats2half2_rn(f0 - fh.x, f1 - fh.y);
    hi = *reinterpret_cast<uint32_t*>(&h);
    lo = *reinterpret_cast<uint32_t*>(&l);
}

// ---- pre-kernel: transpose W [K,N] -> [N,K], prescale, fp16-split, pack ----
__global__ void split_w_kernel(const float* __restrict__ W) {
    int idx = blockIdx.x * blockDim.x + threadIdx.x;   // idx over N*K/2
    if (idx < N_DIM * K_DIM / 2) {
        int n  = idx / (K_DIM / 2);
        int kk = idx - n * (K_DIM / 2);
        float w0 = W[(size_t)(2 * kk)     * N_DIM + n] * WSCALE;
        float w1 = W[(size_t)(2 * kk + 1) * N_DIM + n] * WSCALE;
        uint32_t hi, lo;
        split2(w0, w1, hi, lo);
        g_Wp_hi[idx] = hi;
        g_Wp_lo[idx] = lo;
    }
}

// ---- fused 3xFP16-split mma.sync GEMM + softmax-stats + loss/acc ----
__global__ __launch_bounds__(NTHREADS, 1)
void fused_kernel(const float* __restrict__ x,
                  const float* __restrict__ bias,
                  const int* __restrict__ tags,
                  const float* __restrict__ t2s,
                  const int* __restrict__ tptr,
                  int M)
{
    extern __shared__ uint32_t smem[];
    float* smf = (float*)smem;
    const int tid  = threadIdx.x;
    const int w    = tid >> 5;
    const int lane = tid & 31;
    const int g    = lane >> 2;   // 0..7
    const int t    = lane & 3;    // 0..3
    const int m0   = blockIdx.x * BM;

    if (tid < N_DIM) smf[U_BIAS + tid] = bias[tid];

    // x staging: thread tid stages row tid (16 floats per chunk)
    int arow = m0 + tid; if (arow >= M) arow = M - 1;
    const float* xrow = x + (size_t)arow * K_DIM;
    // W staging: thread stages n = tid>>2, u32 pair at (tid&3)*2
    const int wn = tid >> 2;
    const int wq = (tid & 3) * 2;
    const uint32_t* whp = g_Wp_hi + (size_t)wn * (K_DIM / 2) + wq;
    const uint32_t* wlp = g_Wp_lo + (size_t)wn * (K_DIM / 2) + wq;

    float acc[2][8][4];
    #pragma unroll
    for (int mt = 0; mt < 2; mt++)
        #pragma unroll
        for (int nt = 0; nt < 8; nt++)
            #pragma unroll
            for (int q = 0; q < 4; q++) acc[mt][nt][q] = 0.f;

    // prologue LDG chunk 0
    float4 xa[4]; uint2 wh, wl;
    #pragma unroll
    for (int q = 0; q < 4; q++) xa[q] = *(const float4*)(xrow + 4 * q);
    wh = *(const uint2*)whp;
    wl = *(const uint2*)wlp;

    int buf = 0;
    for (int c = 0; c < NCHUNK; ++c) {
        uint32_t* S = smem + U_BUF + buf * U_BUFSZ;

        // ---- stage: fp16-split x -> packed hi/lo; store pre-split W ----
        {
            uint32_t xh[8], xl[8];
            #pragma unroll
            for (int q = 0; q < 4; q++) {
                split2(xa[q].x, xa[q].y, xh[2 * q],     xl[2 * q]);
                split2(xa[q].z, xa[q].w, xh[2 * q + 1], xl[2 * q + 1]);
            }
            uint4* ph = (uint4*)(S + U_XHI + tid * STRIDE_U);
            uint4* pl = (uint4*)(S + U_XLO + tid * STRIDE_U);
            ph[0] = make_uint4(xh[0], xh[1], xh[2], xh[3]);
            ph[1] = make_uint4(xh[4], xh[5], xh[6], xh[7]);
            pl[0] = make_uint4(xl[0], xl[1], xl[2], xl[3]);
            pl[1] = make_uint4(xl[4], xl[5], xl[6], xl[7]);
            *(uint2*)(S + U_WHI + wn * STRIDE_U + wq) = wh;
            *(uint2*)(S + U_WLO + wn * STRIDE_U + wq) = wl;
        }

        __syncthreads();

        // prefetch next chunk
        if (c + 1 < NCHUNK) {
            const float* xp = xrow + (c + 1) * BK;
            #pragma unroll
            for (int q = 0; q < 4; q++) xa[q] = *(const float4*)(xp + 4 * q);
            wh = *(const uint2*)(whp + (c + 1) * 8);
            wl = *(const uint2*)(wlp + (c + 1) * 8);
        }

        // ---- compute: one k16 step, 48 MMAs ----
        {
            uint32_t ah[2][4], al[2][4];
            #pragma unroll
            for (int mt = 0; mt < 2; mt++) {
                const int r = (32 * w + 16 * mt + g) * STRIDE_U;
                ah[mt][0] = S[U_XHI + r + t];
                ah[mt][1] = S[U_XHI + r + 8 * STRIDE_U + t];
                ah[mt][2] = S[U_XHI + r + 4 + t];
                ah[mt][3] = S[U_XHI + r + 8 * STRIDE_U + 4 + t];
                al[mt][0] = S[U_XLO + r + t];
                al[mt][1] = S[U_XLO + r + 8 * STRIDE_U + t];
                al[mt][2] = S[U_XLO + r + 4 + t];
                al[mt][3] = S[U_XLO + r + 8 * STRIDE_U + 4 + t];
            }
            uint32_t bh[8][2], bl[8][2];
            #pragma unroll
            for (int nt = 0; nt < 8; nt++) {
                const int bidx = (8 * nt + g) * STRIDE_U;
                bh[nt][0] = S[U_WHI + bidx + t];
                bh[nt][1] = S[U_WHI + bidx + 4 + t];
                bl[nt][0] = S[U_WLO + bidx + t];
                bl[nt][1] = S[U_WLO + bidx + 4 + t];
            }
            // term-major: same-accumulator MMAs 16 apart (no RAW stalls)
            #pragma unroll
            for (int nt = 0; nt < 8; nt++)
                #pragma unroll
                for (int mt = 0; mt < 2; mt++)
                    mma_f16(acc[mt][nt], ah[mt], bh[nt]);   // hi*hi
            #pragma unroll
            for (int nt = 0; nt < 8; nt++)
                #pragma unroll
                for (int mt = 0; mt < 2; mt++)
                    mma_f16(acc[mt][nt], ah[mt], bl[nt]);   // hi*lo
            #pragma unroll
            for (int nt = 0; nt < 8; nt++)
                #pragma unroll
                for (int mt = 0; mt < 2; mt++)
                    mma_f16(acc[mt][nt], al[mt], bh[nt]);   // lo*hi
        }
        buf ^= 1;
    }

    // ---- epilogue: quad owns rows; lane holds cols 8*nt + 2*t + j ----
    const int   tval = *tptr;
    const float E1   = 2.718281828459045f;
    float myLoss = 0.f;
    int myRight = 0, myCount = 0;

    #pragma unroll
    for (int mt = 0; mt < 2; mt++) {
        #pragma unroll
        for (int half = 0; half < 2; half++) {
            const int grow = m0 + 32 * w + 16 * mt + 8 * half + g;
            float v[16];
            float lmax = -1e30f, lsum = 0.f;
            int lidx = 0;
            #pragma unroll
            for (int nt = 0; nt < 8; nt++) {
                #pragma unroll
                for (int j = 0; j < 2; j++) {
                    const int col = 8 * nt + 2 * t + j;
                    float f = acc[mt][nt][2 * half + j] * INV_WSCALE + smf[U_BIAS + col];
                    v[2 * nt + j] = f;
                    lsum += f;
                    if (f > lmax) { lmax = f; lidx = col; }
                }
            }
            #pragma unroll
            for (int o = 1; o < 4; o <<= 1) {
                float om = __shfl_xor_sync(0xffffffffu, lmax, o, 4);
                int   oi = __shfl_xor_sync(0xffffffffu, lidx, o, 4);
                if (om > lmax || (om == lmax && oi < lidx)) { lmax = om; lidx = oi; }
            }
            float z = 0.f;
            #pragma unroll
            for (int q = 0; q < 16; q++) z += __expf(v[q] - lmax);
            #pragma unroll
            for (int o = 1; o < 4; o <<= 1) {
                z    += __shfl_xor_sync(0xffffffffu, z,    o, 4);
                lsum += __shfl_xor_sync(0xffffffffu, lsum, o, 4);
            }

            if (grow < M) {
                const int tg = tags[grow];
                if (((tg >> 1) & 3) == t) {
                    float ltag = v[0];
                    #pragma unroll
                    for (int nt = 0; nt < 8; nt++)
                        #pragma unroll
                        for (int j = 0; j < 2; j++)
                            if (tg == 8 * nt + 2 * t + j) ltag = v[2 * nt + j];

                    float logZ   = __logf(z);
                    float lp_tag = ltag - lmax - logZ;
                    float S_log  = lsum - 64.f * (lmax + logZ);
                    float s  = t2s[tg];
                    float sc = powf(s, (float)tval);
                    float es = __expf(sc);
                    float Zy = 63.f * E1 + es;
                    float y_non = E1 / Zy;
                    float y_hot = es / Zy;
                    myLoss -= y_non * S_log + (y_hot - y_non) * lp_tag;
                    if (tg < N_DIM - 3) { myCount++; if (lidx == tg) myRight++; }
                }
            }
        }
    }

    // ---- deterministic block tree-reduction (reuse stage smem) ----
    __syncthreads();
    float* rl = smf + U_BUF;
    int*   rr = (int*)(smem + U_BUF + NTHREADS);
    int*   rc = (int*)(smem + U_BUF + 2 * NTHREADS);
    rl[tid] = myLoss; rr[tid] = myRight; rc[tid] = myCount;
    __syncthreads();
    #pragma unroll
    for (int s2 = NTHREADS / 2; s2 > 0; s2 >>= 1) {
        if (tid < s2) { rl[tid] += rl[tid + s2]; rr[tid] += rr[tid + s2]; rc[tid] += rc[tid + s2]; }
        __syncthreads();
    }
    if (tid == 0) {
        g_partLoss[blockIdx.x]  = rl[0];
        g_partRight[blockIdx.x] = rr[0];
        g_partCount[blockIdx.x] = rc[0];
    }
}

__global__ void finalize_kernel(float* __restrict__ out, int nb)
{
    __shared__ float sl[256];
    __shared__ int   sr[256];
    __shared__ int   sc[256];
    const int t = threadIdx.x;
    float L = 0.f; int R = 0, C = 0;
    for (int i = t; i < nb; i += 256) {
        L += g_partLoss[i]; R += g_partRight[i]; C += g_partCount[i];
    }
    sl[t] = L; sr[t] = R; sc[t] = C;
    __syncthreads();
    for (int s = 128; s > 0; s >>= 1) {
        if (t < s) { sl[t] += sl[t + s]; sr[t] += sr[t + s]; sc[t] += sc[t + s]; }
        __syncthreads();
    }
    if (t == 0) {
        out[0] = sl[0];
        out[1] = (float)sr[0] / (float)sc[0];
    }
}

extern "C" void kernel_launch(void* const* d_in, const int* in_sizes, int n_in,
                              void* d_out, int out_size)
{
    // metadata order: x, W, b, tags, attention_mask, tag_to_score, t
    const float* x    = (const float*)d_in[0];
    const float* W    = (const float*)d_in[1];
    const float* b    = (const float*)d_in[2];
    const int*   tags = (const int*)d_in[3];
    // d_in[4] attention_mask: uniform additive shift over softmax axis -> no-op
    const float* t2s  = (const float*)d_in[5];
    const int*   tptr = (const int*)d_in[6];

    const int M = in_sizes[3];                   // 32768
    int nblocks = (M + BM - 1) / BM;             // 128
    if (nblocks > MAX_BLOCKS) nblocks = MAX_BLOCKS;

    cudaFuncSetAttribute(fused_kernel, cudaFuncAttributeMaxDynamicSharedMemorySize, SMEM_BYTES);

    split_w_kernel<<<(N_DIM * K_DIM / 2 + 255) / 256, 256>>>(W);
    fused_kernel<<<nblocks, NTHREADS, SMEM_BYTES>>>(x, b, tags, t2s, tptr, M);
    finalize_kernel<<<1, 256>>>((float*)d_out, nblocks);
}